// round 9
// baseline (speedup 1.0000x reference)
#include <cuda_runtime.h>

#define H 51
#define BB 16
#define NTHREADS 352
#define KHALF 26
#define HOFF 424                 // floats: 26*16+8 -> 1696B ≡ 32 (mod 128)
#define HSTRIDE 840              // floats per h buffer: 52*16 + 8 gap
#define HT2OFF (2*HSTRIDE + 20)  // hT2 base 6800B ≡ 16 (mod 128)

typedef unsigned long long ull;

#define FFMA2(d, a, b_) asm("fma.rn.f32x2 %0, %1, %2, %0;" : "+l"(d) : "l"(a), "l"(b_))
#define ADDF2(d, a)     asm("add.rn.f32x2 %0, %0, %1;"     : "+l"(d) : "l"(a))

__device__ __forceinline__ ull pack2(float lo, float hi) {
    ull r;
    asm("mov.b64 %0, {%1,%2};" : "=l"(r) : "f"(lo), "f"(hi));
    return r;
}
__device__ __forceinline__ float2 unpack2(ull v) {
    float lo, hi;
    asm("mov.b64 {%0,%1}, %2;" : "=f"(lo), "=f"(hi) : "l"(v));
    return make_float2(lo, hi);
}
__device__ __forceinline__ float sigf(float v) {
    return __fdividef(1.0f, 1.0f + __expf(-v));
}
__device__ __forceinline__ float tanh_f(float v) {
    return 1.0f - __fdividef(2.0f, __expf(2.0f * v) + 1.0f);
}
__device__ __forceinline__ int hidx(int k) { return k * 16 + (k >= KHALF ? 8 : 0); }

__global__ __launch_bounds__(NTHREADS, 1)
void gru2_kernel(const float* __restrict__ input,
                 const float* __restrict__ w_ih1, const float* __restrict__ w_hh1,
                 const float* __restrict__ b_ih1, const float* __restrict__ b_hh1,
                 const float* __restrict__ w_ih2, const float* __restrict__ w_hh2,
                 const float* __restrict__ b_ih2, const float* __restrict__ b_hh2,
                 const float* __restrict__ w_lin, const float* __restrict__ b_lin,
                 float* __restrict__ out, int T, int F)
{
    extern __shared__ float sm[];
    float* hT1 = sm;                        // [2][HSTRIDE]
    float* hT2 = sm + HT2OFF;               // [2][HSTRIDE]
    float* xb  = sm + HT2OFF + 2 * HSTRIDE; // [2][16]
    float* A   = xb + 32;                   // [2][16] output accumulators

    const int tid  = threadIdx.x;
    const int lane = tid & 31;
    const int gb0  = blockIdx.x * BB;
    const int TOT  = T + F;

    for (int j = tid; j < HT2OFF + 2 * HSTRIDE; j += NTHREADS) sm[j] = 0.f;
    if (tid < 32) A[tid] = 0.f;

    const bool isL1 = (tid < 102);
    const bool isL2 = (tid >= 104 && tid < 308);
    const bool isH  = (tid >= 308 && tid < 308 + BB);

    int u = 0, half = 0, triple = 0, pxor = 1;
    const float* hpb = hT1;
    float w0[KHALF], w1[KHALF], w2[KHALF];
    ull bias0 = 0, bias1 = 0, bias2v = 0;
    float wi1r = 0, wi1z = 0, wi1n = 0, bi1r = 0, bi1z = 0, bi1n = 0, wl = 0;

    if (isL1) {
        u = tid >> 1; half = tid & 1;
        #pragma unroll
        for (int j = 0; j < KHALF; ++j) {
            int k = half * KHALF + j;
            bool v = (k < H);
            w0[j] = v ? __ldg(&w_hh1[u * H + k]) : 0.f;
            w1[j] = v ? __ldg(&w_hh1[(H + u) * H + k]) : 0.f;
            w2[j] = v ? __ldg(&w_hh1[(2 * H + u) * H + k]) : 0.f;
        }
        if (!half) {
            float b0 = __ldg(&b_hh1[u]), b1 = __ldg(&b_hh1[H + u]), b2 = __ldg(&b_hh1[2 * H + u]);
            bias0 = pack2(b0, b0); bias1 = pack2(b1, b1); bias2v = pack2(b2, b2);
        }
        wi1r = __ldg(&w_ih1[u]);     wi1z = __ldg(&w_ih1[H + u]);     wi1n = __ldg(&w_ih1[2 * H + u]);
        bi1r = __ldg(&b_ih1[u]);     bi1z = __ldg(&b_ih1[H + u]);     bi1n = __ldg(&b_ih1[2 * H + u]);
    } else if (isL2) {
        int l = tid - 104;
        u = l >> 2; l &= 3; triple = l >> 1; half = l & 1;
        const float* wr = triple ? w_ih2 : w_hh2;
        const float* br = triple ? b_ih2 : b_hh2;
        hpb  = triple ? hT1 : hT2;
        pxor = triple ? 1 : 0;
        #pragma unroll
        for (int j = 0; j < KHALF; ++j) {
            int k = half * KHALF + j;
            bool v = (k < H);
            w0[j] = v ? __ldg(&wr[u * H + k]) : 0.f;
            w1[j] = v ? __ldg(&wr[(H + u) * H + k]) : 0.f;
            w2[j] = v ? __ldg(&wr[(2 * H + u) * H + k]) : 0.f;
        }
        if (!half) {
            float b0 = __ldg(&br[u]), b1 = __ldg(&br[H + u]), b2 = __ldg(&br[2 * H + u]);
            bias0 = pack2(b0, b0); bias1 = pack2(b1, b1); bias2v = pack2(b2, b2);
        }
        wl = __ldg(&w_lin[u]);
    } else {
        #pragma unroll
        for (int j = 0; j < KHALF; ++j) { w0[j] = 0.f; w1[j] = 0.f; w2[j] = 0.f; }
    }
    const float blin = __ldg(&b_lin[0]);
    if (isH && T > 0) {
        int j = tid - 308;
        xb[j] = __ldg(&input[(size_t)(gb0 + j) * T]);   // x[0] into parity-0 buffer
    }
    const int hbx = hidx(u);
    __syncthreads();

    for (int i = 0; i <= TOT; ++i) {
        const int par = i & 1;
        ull f0[4], f1[4], f2[4];   // full-k sums for this lane's 8 batches

        // ================= DOT + k-combine =================
        if (isL1 || isL2) {
            const float* hp = hpb + (par ^ pxor) * HSTRIDE + half * HOFF;
            ull a0[8], a1[8], a2[8];
            #pragma unroll
            for (int bp = 0; bp < 8; ++bp) { a0[bp] = bias0; a1[bp] = bias1; a2[bp] = bias2v; }
            #pragma unroll
            for (int k = 0; k < KHALF; ++k) {
                const ulonglong2* q = (const ulonglong2*)(hp + k * 16);
                ulonglong2 q0 = q[0], q1 = q[1], q2 = q[2], q3 = q[3];
                ull wd;
                wd = pack2(w0[k], w0[k]);
                FFMA2(a0[0], wd, q0.x); FFMA2(a0[1], wd, q0.y);
                FFMA2(a0[2], wd, q1.x); FFMA2(a0[3], wd, q1.y);
                FFMA2(a0[4], wd, q2.x); FFMA2(a0[5], wd, q2.y);
                FFMA2(a0[6], wd, q3.x); FFMA2(a0[7], wd, q3.y);
                wd = pack2(w1[k], w1[k]);
                FFMA2(a1[0], wd, q0.x); FFMA2(a1[1], wd, q0.y);
                FFMA2(a1[2], wd, q1.x); FFMA2(a1[3], wd, q1.y);
                FFMA2(a1[4], wd, q2.x); FFMA2(a1[5], wd, q2.y);
                FFMA2(a1[6], wd, q3.x); FFMA2(a1[7], wd, q3.y);
                wd = pack2(w2[k], w2[k]);
                FFMA2(a2[0], wd, q0.x); FFMA2(a2[1], wd, q0.y);
                FFMA2(a2[2], wd, q1.x); FFMA2(a2[3], wd, q1.y);
                FFMA2(a2[4], wd, q2.x); FFMA2(a2[5], wd, q2.y);
                FFMA2(a2[6], wd, q3.x); FFMA2(a2[7], wd, q3.y);
            }
            // combine k-halves: keep my 8 batches, give partner theirs
            const unsigned m1 = 0x3u << (lane & 30);
            const int B0 = 4 * half, G0 = 4 - 4 * half;
            #pragma unroll
            for (int j = 0; j < 4; ++j) {
                ull r;
                r = __shfl_xor_sync(m1, a0[G0 + j], 1); f0[j] = a0[B0 + j]; ADDF2(f0[j], r);
                r = __shfl_xor_sync(m1, a1[G0 + j], 1); f1[j] = a1[B0 + j]; ADDF2(f1[j], r);
                r = __shfl_xor_sync(m1, a2[G0 + j], 1); f2[j] = a2[B0 + j]; ADDF2(f2[j], r);
            }
        }

        // ================= Helpers =================
        if (isH) {
            int j = tid - 308;
            if (i >= 2) out[(size_t)(gb0 + j) * TOT + (i - 2)] = A[(par ^ 1) * 16 + j] + blin;
            A[(par ^ 1) * 16 + j] = 0.f;
            if (i + 1 < T) xb[((i + 1) & 1) * 16 + j] = __ldg(&input[(size_t)(gb0 + j) * T + (i + 1)]);
        }

        // ================= L2 pointwise (produces h2[i-1], o[i-1]) =================
        if (isL2) {
            const unsigned m2 = 0xFu << (lane & 28);
            const int J0 = 2 * triple, Jg = 2 - 2 * triple;
            ull o0[2], o1[2], o2[2];
            #pragma unroll
            for (int j = 0; j < 2; ++j) {
                o0[j] = __shfl_xor_sync(m2, f0[Jg + j], 2);
                o1[j] = __shfl_xor_sync(m2, f1[Jg + j], 2);
                o2[j] = __shfl_xor_sync(m2, f2[Jg + j], 2);
            }
            if (i > 0) {
                const int F0 = 8 * half + 4 * triple;
                float4 hold = *(const float4*)(hT2 + par * HSTRIDE + hbx + F0);
                float hn[4];
                #pragma unroll
                for (int j = 0; j < 2; ++j) {
                    float2 mr = unpack2(f0[J0 + j]), orr = unpack2(o0[j]);
                    float2 mz = unpack2(f1[J0 + j]), oz  = unpack2(o1[j]);
                    float2 mn = unpack2(f2[J0 + j]), onn = unpack2(o2[j]);
                    float hh0 = triple ? onn.x : mn.x, ih0 = triple ? mn.x : onn.x;
                    float hh1 = triple ? onn.y : mn.y, ih1 = triple ? mn.y : onn.y;
                    float r0 = sigf(mr.x + orr.x), r1 = sigf(mr.y + orr.y);
                    float z0 = sigf(mz.x + oz.x),  z1 = sigf(mz.y + oz.y);
                    float n0 = tanh_f(fmaf(r0, hh0, ih0));
                    float n1 = tanh_f(fmaf(r1, hh1, ih1));
                    float ho0 = j ? hold.z : hold.x;
                    float ho1 = j ? hold.w : hold.y;
                    hn[2 * j]     = n0 + z0 * (ho0 - n0);
                    hn[2 * j + 1] = n1 + z1 * (ho1 - n1);
                }
                *(float4*)(hT2 + (par ^ 1) * HSTRIDE + hbx + F0) = make_float4(hn[0], hn[1], hn[2], hn[3]);
                float* oa = A + par * 16 + F0;
                atomicAdd(&oa[0], wl * hn[0]);
                atomicAdd(&oa[1], wl * hn[1]);
                atomicAdd(&oa[2], wl * hn[2]);
                atomicAdd(&oa[3], wl * hn[3]);
            }
        }

        if (i >= T) __syncthreads();   // future mode: A[par] (o[i-1]) must be complete before L1 reads it

        // ================= L1 pointwise (produces h1[i]) =================
        if (isL1) {
            const int F0 = 8 * half;
            float x[8];
            if (i < T) {
                float4 xa = *(const float4*)(xb + par * 16 + F0);
                float4 xc = *(const float4*)(xb + par * 16 + F0 + 4);
                x[0]=xa.x; x[1]=xa.y; x[2]=xa.z; x[3]=xa.w;
                x[4]=xc.x; x[5]=xc.y; x[6]=xc.z; x[7]=xc.w;
            } else {
                float4 xa = *(const float4*)(A + par * 16 + F0);
                float4 xc = *(const float4*)(A + par * 16 + F0 + 4);
                x[0]=xa.x+blin; x[1]=xa.y+blin; x[2]=xa.z+blin; x[3]=xa.w+blin;
                x[4]=xc.x+blin; x[5]=xc.y+blin; x[6]=xc.z+blin; x[7]=xc.w+blin;
            }
            const float* h1c = hT1 + (par ^ 1) * HSTRIDE + hbx + F0;
            float4 hoA = *(const float4*)h1c;
            float4 hoB = *(const float4*)(h1c + 4);
            float ho[8] = {hoA.x, hoA.y, hoA.z, hoA.w, hoB.x, hoB.y, hoB.z, hoB.w};
            float hn[8];
            #pragma unroll
            for (int j = 0; j < 4; ++j) {
                float2 hr = unpack2(f0[j]), hz = unpack2(f1[j]), hv = unpack2(f2[j]);
                float x0 = x[2 * j], x1 = x[2 * j + 1];
                float r0 = sigf(fmaf(x0, wi1r, bi1r) + hr.x);
                float r1 = sigf(fmaf(x1, wi1r, bi1r) + hr.y);
                float z0 = sigf(fmaf(x0, wi1z, bi1z) + hz.x);
                float z1 = sigf(fmaf(x1, wi1z, bi1z) + hz.y);
                float n0 = tanh_f(fmaf(x0, wi1n, bi1n) + r0 * hv.x);
                float n1 = tanh_f(fmaf(x1, wi1n, bi1n) + r1 * hv.y);
                hn[2 * j]     = n0 + z0 * (ho[2 * j] - n0);
                hn[2 * j + 1] = n1 + z1 * (ho[2 * j + 1] - n1);
            }
            float* h1n = hT1 + par * HSTRIDE + hbx + F0;
            *(float4*)h1n       = make_float4(hn[0], hn[1], hn[2], hn[3]);
            *(float4*)(h1n + 4) = make_float4(hn[4], hn[5], hn[6], hn[7]);
        }
        __syncthreads();
    }

    if (tid < BB)
        out[(size_t)(gb0 + tid) * TOT + (TOT - 1)] = A[(TOT & 1) * 16 + tid] + blin;
}

extern "C" void kernel_launch(void* const* d_in, const int* in_sizes, int n_in,
                              void* d_out, int out_size) {
    const float* input = (const float*)d_in[0];
    const float* w_ih1 = (const float*)d_in[2];
    const float* w_hh1 = (const float*)d_in[3];
    const float* b_ih1 = (const float*)d_in[4];
    const float* b_hh1 = (const float*)d_in[5];
    const float* w_ih2 = (const float*)d_in[6];
    const float* w_hh2 = (const float*)d_in[7];
    const float* b_ih2 = (const float*)d_in[8];
    const float* b_hh2 = (const float*)d_in[9];
    const float* w_lin = (const float*)d_in[10];
    const float* b_lin = (const float*)d_in[11];

    const int B   = 2048;
    const int T   = in_sizes[0] / B;
    const int TOT = out_size / B;
    const int F   = TOT - T;

    size_t smem = (size_t)(HT2OFF + 2 * HSTRIDE + 64) * sizeof(float);
    cudaFuncSetAttribute(gru2_kernel, cudaFuncAttributeMaxDynamicSharedMemorySize, (int)smem);

    gru2_kernel<<<B / BB, NTHREADS, smem>>>(
        input, w_ih1, w_hh1, b_ih1, b_hh1,
        w_ih2, w_hh2, b_ih2, b_hh2,
        w_lin, b_lin, (float*)d_out, T, F);
}

// round 10
// speedup vs baseline: 1.0039x; 1.0039x over previous
#include <cuda_runtime.h>

#define H 51
#define BB 16
#define NTHREADS 352
#define KHALF 26
#define HOFF 424                 // floats: 26*16+8 -> 1696B ≡ 32 (mod 128)
#define HSTRIDE 840              // floats per h buffer: 52*16 + 8 gap
#define HT2OFF (2*HSTRIDE + 20)  // hT2 base 6800B ≡ 16 (mod 128)

typedef unsigned long long ull;

#define FFMA2(d, a, b_) asm("fma.rn.f32x2 %0, %1, %2, %0;" : "+l"(d) : "l"(a), "l"(b_))
#define ADDF2(d, a)     asm("add.rn.f32x2 %0, %0, %1;"     : "+l"(d) : "l"(a))

__device__ __forceinline__ ull pack2(float lo, float hi) {
    ull r;
    asm("mov.b64 %0, {%1,%2};" : "=l"(r) : "f"(lo), "f"(hi));
    return r;
}
__device__ __forceinline__ float2 unpack2(ull v) {
    float lo, hi;
    asm("mov.b64 {%0,%1}, %2;" : "=f"(lo), "=f"(hi) : "l"(v));
    return make_float2(lo, hi);
}
__device__ __forceinline__ float sigf(float v) {
    return __fdividef(1.0f, 1.0f + __expf(-v));
}
__device__ __forceinline__ float tanh_f(float v) {
    return 1.0f - __fdividef(2.0f, __expf(2.0f * v) + 1.0f);
}
__device__ __forceinline__ int hidx(int k) { return k * 16 + (k >= KHALF ? 8 : 0); }

__global__ __launch_bounds__(NTHREADS, 1)
void gru2_kernel(const float* __restrict__ input,
                 const float* __restrict__ w_ih1, const float* __restrict__ w_hh1,
                 const float* __restrict__ b_ih1, const float* __restrict__ b_hh1,
                 const float* __restrict__ w_ih2, const float* __restrict__ w_hh2,
                 const float* __restrict__ b_ih2, const float* __restrict__ b_hh2,
                 const float* __restrict__ w_lin, const float* __restrict__ b_lin,
                 float* __restrict__ out, int T, int F)
{
    extern __shared__ float sm[];
    float* hT1 = sm;                        // [2][HSTRIDE]
    float* hT2 = sm + HT2OFF;               // [2][HSTRIDE]
    float* xb  = sm + HT2OFF + 2 * HSTRIDE; // [2][16]
    float* A   = xb + 32;                   // [2][16] output accumulators

    const int tid  = threadIdx.x;
    const int lane = tid & 31;
    const int gb0  = blockIdx.x * BB;
    const int TOT  = T + F;

    for (int j = tid; j < HT2OFF + 2 * HSTRIDE; j += NTHREADS) sm[j] = 0.f;
    if (tid < 32) A[tid] = 0.f;

    const bool isL1 = (tid < 102);
    const bool isL2 = (tid >= 104 && tid < 308);
    const bool isH  = (tid >= 308 && tid < 308 + BB);

    int u = 0, half = 0, triple = 0, pxor = 1;
    const float* hpb = hT1;
    float w0[KHALF], w1[KHALF], w2[KHALF];
    ull bias0 = 0, bias1 = 0, bias2v = 0;
    float wi1r = 0, wi1z = 0, wi1n = 0, bi1r = 0, bi1z = 0, bi1n = 0, wl = 0;

    if (isL1) {
        u = tid >> 1; half = tid & 1;
        #pragma unroll
        for (int j = 0; j < KHALF; ++j) {
            int k = half * KHALF + j;
            bool v = (k < H);
            w0[j] = v ? __ldg(&w_hh1[u * H + k]) : 0.f;
            w1[j] = v ? __ldg(&w_hh1[(H + u) * H + k]) : 0.f;
            w2[j] = v ? __ldg(&w_hh1[(2 * H + u) * H + k]) : 0.f;
        }
        if (!half) {
            float b0 = __ldg(&b_hh1[u]), b1 = __ldg(&b_hh1[H + u]), b2 = __ldg(&b_hh1[2 * H + u]);
            bias0 = pack2(b0, b0); bias1 = pack2(b1, b1); bias2v = pack2(b2, b2);
        }
        wi1r = __ldg(&w_ih1[u]);     wi1z = __ldg(&w_ih1[H + u]);     wi1n = __ldg(&w_ih1[2 * H + u]);
        bi1r = __ldg(&b_ih1[u]);     bi1z = __ldg(&b_ih1[H + u]);     bi1n = __ldg(&b_ih1[2 * H + u]);
    } else if (isL2) {
        int l = tid - 104;
        u = l >> 2; l &= 3; triple = l >> 1; half = l & 1;
        const float* wr = triple ? w_ih2 : w_hh2;
        const float* br = triple ? b_ih2 : b_hh2;
        hpb  = triple ? hT1 : hT2;
        pxor = triple ? 1 : 0;
        #pragma unroll
        for (int j = 0; j < KHALF; ++j) {
            int k = half * KHALF + j;
            bool v = (k < H);
            w0[j] = v ? __ldg(&wr[u * H + k]) : 0.f;
            w1[j] = v ? __ldg(&wr[(H + u) * H + k]) : 0.f;
            w2[j] = v ? __ldg(&wr[(2 * H + u) * H + k]) : 0.f;
        }
        if (!half) {
            float b0 = __ldg(&br[u]), b1 = __ldg(&br[H + u]), b2 = __ldg(&br[2 * H + u]);
            bias0 = pack2(b0, b0); bias1 = pack2(b1, b1); bias2v = pack2(b2, b2);
        }
        wl = __ldg(&w_lin[u]);
    } else {
        #pragma unroll
        for (int j = 0; j < KHALF; ++j) { w0[j] = 0.f; w1[j] = 0.f; w2[j] = 0.f; }
    }
    const float blin = __ldg(&b_lin[0]);
    if (isH && T > 0) {
        int j = tid - 308;
        xb[j] = __ldg(&input[(size_t)(gb0 + j) * T]);   // x[0] into parity-0 buffer
    }
    const int hbx = hidx(u);
    __syncthreads();

    for (int i = 0; i <= TOT; ++i) {
        const int par = i & 1;
        ull f0[4], f1[4], f2[4];   // full-k sums for this lane's 8 batches

        // ================= DOT + k-combine =================
        if (isL1 || isL2) {
            const float* hp = hpb + (par ^ pxor) * HSTRIDE + half * HOFF;
            ull a0[8], a1[8], a2[8];
            #pragma unroll
            for (int bp = 0; bp < 8; ++bp) { a0[bp] = bias0; a1[bp] = bias1; a2[bp] = bias2v; }
            #pragma unroll
            for (int k = 0; k < KHALF; ++k) {
                const ulonglong2* q = (const ulonglong2*)(hp + k * 16);
                ulonglong2 q0 = q[0], q1 = q[1], q2 = q[2], q3 = q[3];
                ull wd;
                wd = pack2(w0[k], w0[k]);
                FFMA2(a0[0], wd, q0.x); FFMA2(a0[1], wd, q0.y);
                FFMA2(a0[2], wd, q1.x); FFMA2(a0[3], wd, q1.y);
                FFMA2(a0[4], wd, q2.x); FFMA2(a0[5], wd, q2.y);
                FFMA2(a0[6], wd, q3.x); FFMA2(a0[7], wd, q3.y);
                wd = pack2(w1[k], w1[k]);
                FFMA2(a1[0], wd, q0.x); FFMA2(a1[1], wd, q0.y);
                FFMA2(a1[2], wd, q1.x); FFMA2(a1[3], wd, q1.y);
                FFMA2(a1[4], wd, q2.x); FFMA2(a1[5], wd, q2.y);
                FFMA2(a1[6], wd, q3.x); FFMA2(a1[7], wd, q3.y);
                wd = pack2(w2[k], w2[k]);
                FFMA2(a2[0], wd, q0.x); FFMA2(a2[1], wd, q0.y);
                FFMA2(a2[2], wd, q1.x); FFMA2(a2[3], wd, q1.y);
                FFMA2(a2[4], wd, q2.x); FFMA2(a2[5], wd, q2.y);
                FFMA2(a2[6], wd, q3.x); FFMA2(a2[7], wd, q3.y);
            }
            // combine k-halves: keep my 8 batches, give partner theirs
            const unsigned m1 = 0x3u << (lane & 30);
            const int B0 = 4 * half, G0 = 4 - 4 * half;
            #pragma unroll
            for (int j = 0; j < 4; ++j) {
                ull r;
                r = __shfl_xor_sync(m1, a0[G0 + j], 1); f0[j] = a0[B0 + j]; ADDF2(f0[j], r);
                r = __shfl_xor_sync(m1, a1[G0 + j], 1); f1[j] = a1[B0 + j]; ADDF2(f1[j], r);
                r = __shfl_xor_sync(m1, a2[G0 + j], 1); f2[j] = a2[B0 + j]; ADDF2(f2[j], r);
            }
        }

        // ================= Helpers =================
        if (isH) {
            int j = tid - 308;
            if (i >= 2) out[(size_t)(gb0 + j) * TOT + (i - 2)] = A[(par ^ 1) * 16 + j] + blin;
            A[(par ^ 1) * 16 + j] = 0.f;
            if (i + 1 < T) xb[((i + 1) & 1) * 16 + j] = __ldg(&input[(size_t)(gb0 + j) * T + (i + 1)]);
        }

        // ================= L2 pointwise (produces h2[i-1], o[i-1]) =================
        if (isL2) {
            const unsigned m2 = 0xFu << (lane & 28);
            const int J0 = 2 * triple, Jg = 2 - 2 * triple;
            ull o0[2], o1[2], o2[2];
            #pragma unroll
            for (int j = 0; j < 2; ++j) {
                o0[j] = __shfl_xor_sync(m2, f0[Jg + j], 2);
                o1[j] = __shfl_xor_sync(m2, f1[Jg + j], 2);
                o2[j] = __shfl_xor_sync(m2, f2[Jg + j], 2);
            }
            if (i > 0) {
                const int F0 = 8 * half + 4 * triple;
                float4 hold = *(const float4*)(hT2 + par * HSTRIDE + hbx + F0);
                float hn[4];
                #pragma unroll
                for (int j = 0; j < 2; ++j) {
                    float2 mr = unpack2(f0[J0 + j]), orr = unpack2(o0[j]);
                    float2 mz = unpack2(f1[J0 + j]), oz  = unpack2(o1[j]);
                    float2 mn = unpack2(f2[J0 + j]), onn = unpack2(o2[j]);
                    float hh0 = triple ? onn.x : mn.x, ih0 = triple ? mn.x : onn.x;
                    float hh1 = triple ? onn.y : mn.y, ih1 = triple ? mn.y : onn.y;
                    float r0 = sigf(mr.x + orr.x), r1 = sigf(mr.y + orr.y);
                    float z0 = sigf(mz.x + oz.x),  z1 = sigf(mz.y + oz.y);
                    float n0 = tanh_f(fmaf(r0, hh0, ih0));
                    float n1 = tanh_f(fmaf(r1, hh1, ih1));
                    float ho0 = j ? hold.z : hold.x;
                    float ho1 = j ? hold.w : hold.y;
                    hn[2 * j]     = n0 + z0 * (ho0 - n0);
                    hn[2 * j + 1] = n1 + z1 * (ho1 - n1);
                }
                *(float4*)(hT2 + (par ^ 1) * HSTRIDE + hbx + F0) = make_float4(hn[0], hn[1], hn[2], hn[3]);
                float* oa = A + par * 16 + F0;
                atomicAdd(&oa[0], wl * hn[0]);
                atomicAdd(&oa[1], wl * hn[1]);
                atomicAdd(&oa[2], wl * hn[2]);
                atomicAdd(&oa[3], wl * hn[3]);
            }
        }

        if (i >= T) __syncthreads();   // future mode: A[par] (o[i-1]) must be complete before L1 reads it

        // ================= L1 pointwise (produces h1[i]) =================
        if (isL1) {
            const int F0 = 8 * half;
            float x[8];
            if (i < T) {
                float4 xa = *(const float4*)(xb + par * 16 + F0);
                float4 xc = *(const float4*)(xb + par * 16 + F0 + 4);
                x[0]=xa.x; x[1]=xa.y; x[2]=xa.z; x[3]=xa.w;
                x[4]=xc.x; x[5]=xc.y; x[6]=xc.z; x[7]=xc.w;
            } else {
                float4 xa = *(const float4*)(A + par * 16 + F0);
                float4 xc = *(const float4*)(A + par * 16 + F0 + 4);
                x[0]=xa.x+blin; x[1]=xa.y+blin; x[2]=xa.z+blin; x[3]=xa.w+blin;
                x[4]=xc.x+blin; x[5]=xc.y+blin; x[6]=xc.z+blin; x[7]=xc.w+blin;
            }
            const float* h1c = hT1 + (par ^ 1) * HSTRIDE + hbx + F0;
            float4 hoA = *(const float4*)h1c;
            float4 hoB = *(const float4*)(h1c + 4);
            float ho[8] = {hoA.x, hoA.y, hoA.z, hoA.w, hoB.x, hoB.y, hoB.z, hoB.w};
            float hn[8];
            #pragma unroll
            for (int j = 0; j < 4; ++j) {
                float2 hr = unpack2(f0[j]), hz = unpack2(f1[j]), hv = unpack2(f2[j]);
                float x0 = x[2 * j], x1 = x[2 * j + 1];
                float r0 = sigf(fmaf(x0, wi1r, bi1r) + hr.x);
                float r1 = sigf(fmaf(x1, wi1r, bi1r) + hr.y);
                float z0 = sigf(fmaf(x0, wi1z, bi1z) + hz.x);
                float z1 = sigf(fmaf(x1, wi1z, bi1z) + hz.y);
                float n0 = tanh_f(fmaf(x0, wi1n, bi1n) + r0 * hv.x);
                float n1 = tanh_f(fmaf(x1, wi1n, bi1n) + r1 * hv.y);
                hn[2 * j]     = n0 + z0 * (ho[2 * j] - n0);
                hn[2 * j + 1] = n1 + z1 * (ho[2 * j + 1] - n1);
            }
            float* h1n = hT1 + par * HSTRIDE + hbx + F0;
            *(float4*)h1n       = make_float4(hn[0], hn[1], hn[2], hn[3]);
            *(float4*)(h1n + 4) = make_float4(hn[4], hn[5], hn[6], hn[7]);
        }
        __syncthreads();
    }

    if (tid < BB)
        out[(size_t)(gb0 + tid) * TOT + (TOT - 1)] = A[(TOT & 1) * 16 + tid] + blin;
}

extern "C" void kernel_launch(void* const* d_in, const int* in_sizes, int n_in,
                              void* d_out, int out_size) {
    const float* input = (const float*)d_in[0];
    const float* w_ih1 = (const float*)d_in[2];
    const float* w_hh1 = (const float*)d_in[3];
    const float* b_ih1 = (const float*)d_in[4];
    const float* b_hh1 = (const float*)d_in[5];
    const float* w_ih2 = (const float*)d_in[6];
    const float* w_hh2 = (const float*)d_in[7];
    const float* b_ih2 = (const float*)d_in[8];
    const float* b_hh2 = (const float*)d_in[9];
    const float* w_lin = (const float*)d_in[10];
    const float* b_lin = (const float*)d_in[11];

    const int B   = 2048;
    const int T   = in_sizes[0] / B;
    const int TOT = out_size / B;
    const int F   = TOT - T;

    size_t smem = (size_t)(HT2OFF + 2 * HSTRIDE + 64) * sizeof(float);
    cudaFuncSetAttribute(gru2_kernel, cudaFuncAttributeMaxDynamicSharedMemorySize, (int)smem);

    gru2_kernel<<<B / BB, NTHREADS, smem>>>(
        input, w_ih1, w_hh1, b_ih1, b_hh1,
        w_ih2, w_hh2, b_ih2, b_hh2,
        w_lin, b_lin, (float*)d_out, T, F);
}

// round 12
// speedup vs baseline: 2.2761x; 2.2672x over previous
#include <cuda_runtime.h>

#define H 51
#define BB 16
#define NTHREADS 512
#define NPAIRS 231       // 3 regions x 77 row-pairs (regions padded 153->154)
#define NDOT 462         // 2 threads per pair (k-split)
#define KHALF 26         // k's per half (pad 51 -> 52)
#define HOFF 424         // half-1 k-range float offset: 26*16 + 8 -> 1696B ≡ 32 mod 128
#define HSTRIDE 840      // floats per h buffer: 52*16 + 8 gap
#define GROWS 462        // gbuf rows: 3 regions x 154
#define GPU 9            // gbuf pitch (float2 / ull units)
#define GPF 18           // gbuf pitch (floats)
#define GR2 154
#define GR3 308
#define REDS 208         // red floats per parity: 13 warps x 16 batches

typedef unsigned long long ull;

#define FFMA2(d, a, b_) asm("fma.rn.f32x2 %0, %1, %2, %0;" : "+l"(d) : "l"(a), "l"(b_))
#define ADDF2(d, a)     asm("add.rn.f32x2 %0, %0, %1;"     : "+l"(d) : "l"(a))

__device__ __forceinline__ ull pack2(float lo, float hi) {
    ull r;
    asm("mov.b64 %0, {%1,%2};" : "=l"(r) : "f"(lo), "f"(hi));
    return r;
}
__device__ __forceinline__ float2 unpack2(ull v) {
    float lo, hi;
    asm("mov.b64 {%0,%1}, %2;" : "=f"(lo), "=f"(hi) : "l"(v));
    return make_float2(lo, hi);
}
__device__ __forceinline__ float sigf(float v) {
    return __fdividef(1.0f, 1.0f + __expf(-v));
}
__device__ __forceinline__ float tanh_f(float v) {
    return 1.0f - __fdividef(2.0f, __expf(2.0f * v) + 1.0f);
}
// h element index with mid-gap: k<26 -> k*16, k>=26 -> k*16 + 8
__device__ __forceinline__ int hidx(int k) { return k * 16 + (k >= KHALF ? 8 : 0); }

__global__ __launch_bounds__(NTHREADS, 1)
void gru2_kernel(const float* __restrict__ input,
                 const float* __restrict__ w_ih1, const float* __restrict__ w_hh1,
                 const float* __restrict__ b_ih1, const float* __restrict__ b_hh1,
                 const float* __restrict__ w_ih2, const float* __restrict__ w_hh2,
                 const float* __restrict__ b_ih2, const float* __restrict__ b_hh2,
                 const float* __restrict__ w_lin, const float* __restrict__ b_lin,
                 float* __restrict__ out, int T, int F)
{
    extern __shared__ float sm[];
    float* hT1   = sm;                         // [2][HSTRIDE]
    float* hT2   = hT1 + 2 * HSTRIDE;          // [2][HSTRIDE]
    ull*   gbufU = (ull*)(sm + 4 * HSTRIDE);   // [462][9]
    float* gbufF = (float*)gbufU;
    const float2* g2 = (const float2*)gbufF;
    float* tabs  = (float*)(gbufU + GROWS * GPU);  // 7*51 + 1 pad
    float* xbuf  = tabs + 7 * H + 1;           // [16], 8B aligned
    float* oacc  = xbuf + BB;                  // [2][16]
    float* red   = oacc + 2 * BB;              // [2][13][16]

    const int tid  = threadIdx.x;
    const int lane = tid & 31;
    const int gb0  = blockIdx.x * BB;
    const int TOT  = T + F;

    for (int j = tid; j < 4 * HSTRIDE; j += NTHREADS) sm[j] = 0.f;
    if (tid < H) {
        tabs[tid]         = __ldg(&w_ih1[tid]);
        tabs[H + tid]     = __ldg(&w_ih1[H + tid]);
        tabs[2 * H + tid] = __ldg(&w_ih1[2 * H + tid]);
        tabs[3 * H + tid] = __ldg(&b_ih1[tid]);
        tabs[4 * H + tid] = __ldg(&b_ih1[H + tid]);
        tabs[5 * H + tid] = __ldg(&b_ih1[2 * H + tid]);
        tabs[6 * H + tid] = __ldg(&w_lin[tid]);
    }

    // ---- dot-thread setup (identical to R7) ----
    const bool comp = (tid < NDOT);
    const int P    = comp ? (tid >> 1) : 0;
    const int half = tid & 1;
    const unsigned pmask = 0x3u << (tid & 30);

    const int region = P / 77;
    const int q      = P - region * 77;
    const int ra = 2 * q, rb = 2 * q + 1;
    const bool vB = (rb < 153);
    const float* base = (region == 0) ? w_hh1 : ((region == 1) ? w_hh2 : w_ih2);
    const float* bsrc = (region == 0) ? b_hh1 : ((region == 1) ? b_hh2 : b_ih2);
    const int hsel = (region == 1);

    float wA[KHALF], wB[KHALF];
    #pragma unroll
    for (int j = 0; j < KHALF; ++j) {
        int k = half * KHALF + j;
        wA[j] = (comp && k < H) ? __ldg(&base[ra * H + k]) : 0.f;
        wB[j] = (comp && vB && k < H) ? __ldg(&base[rb * H + k]) : 0.f;
    }
    float bA  = comp ? __ldg(&bsrc[ra]) : 0.f;
    float bBv = (comp && vB) ? __ldg(&bsrc[rb]) : 0.f;
    const ull biasA = half ? 0ULL : pack2(bA, bA);
    const ull biasB = half ? 0ULL : pack2(bBv, bBv);
    const float blin = __ldg(&b_lin[0]);
    const int pxor = hsel ? 0 : 1;
    const float* hbase = hsel ? hT2 : hT1;
    const int hoff = half * HOFF;
    const int growA = region * 154 + ra;
    const int growB = region * 154 + rb;

    __syncthreads();

    for (int i = 0; i <= TOT; ++i) {
        const int par = i & 1;

        // ================= DOT STAGE (R7 core) + helper warp 15 =================
        if (comp) {
            const float* hp = hbase + (par ^ pxor) * HSTRIDE + hoff;
            ull aA[8], aB[8];
            #pragma unroll
            for (int bp = 0; bp < 8; ++bp) { aA[bp] = biasA; aB[bp] = biasB; }
            #pragma unroll
            for (int k = 0; k < KHALF; ++k) {
                const ull wdA = pack2(wA[k], wA[k]);
                const ull wdB = pack2(wB[k], wB[k]);
                const ulonglong2* qq = (const ulonglong2*)(hp + k * 16);
                ulonglong2 q0 = qq[0], q1 = qq[1], q2 = qq[2], q3 = qq[3];
                FFMA2(aA[0], wdA, q0.x); FFMA2(aA[1], wdA, q0.y);
                FFMA2(aA[2], wdA, q1.x); FFMA2(aA[3], wdA, q1.y);
                FFMA2(aA[4], wdA, q2.x); FFMA2(aA[5], wdA, q2.y);
                FFMA2(aA[6], wdA, q3.x); FFMA2(aA[7], wdA, q3.y);
                FFMA2(aB[0], wdB, q0.x); FFMA2(aB[1], wdB, q0.y);
                FFMA2(aB[2], wdB, q1.x); FFMA2(aB[3], wdB, q1.y);
                FFMA2(aB[4], wdB, q2.x); FFMA2(aB[5], wdB, q2.y);
                FFMA2(aB[6], wdB, q3.x); FFMA2(aB[7], wdB, q3.y);
            }
            #pragma unroll
            for (int bp = 0; bp < 8; ++bp) {
                ull oA = __shfl_xor_sync(pmask, aA[bp], 1);
                ull oB = __shfl_xor_sync(pmask, aB[bp], 1);
                ADDF2(aA[bp], oA);
                ADDF2(aB[bp], oB);
            }
            if (!half) {
                ull* goA = gbufU + growA * GPU;
                ull* goB = gbufU + growB * GPU;
                #pragma unroll
                for (int bp = 0; bp < 8; ++bp) { goA[bp] = aA[bp]; goB[bp] = aB[bp]; }
            }
        } else if (tid >= 480) {
            // helper warp 15: finalize o[i-2] from red scratch; x prefetch; oacc zero
            int l = tid - 480;
            if (i >= 2 && i <= T) {
                int b = l & 15, hf = l >> 4;
                const float* rr = red + (par ^ 1) * REDS;
                float s = 0.f;
                #pragma unroll
                for (int r = 0; r < 7; ++r) {
                    int row = hf * 7 + r;
                    if (row < 13) s += rr[row * 16 + b];
                }
                s += __shfl_xor_sync(0xFFFFFFFFu, s, 16);
                if (hf == 0) out[(size_t)(gb0 + b) * TOT + (i - 2)] = s + blin;
            }
            if (l < BB) {
                if (i >= T) oacc[par * 16 + l] = 0.f;
                if (i < T)  xbuf[l] = __ldg(&input[(size_t)(gb0 + l) * T + i]);
            }
        }
        __syncthreads();

        // ================= POINTWISE STAGE =================
        float* h2c = hT2 + par * HSTRIDE;          // h2[i-2]
        float* h2n = hT2 + (par ^ 1) * HSTRIDE;    // h2[i-1]
        float* h1c = hT1 + (par ^ 1) * HSTRIDE;    // h1[i-1]
        float* h1n = hT1 + par * HSTRIDE;          // h1[i]

        if (i < T) {
            // ---- L2 pointwise + warp reduction into red (warps 0-12, full) ----
            if (i > 0 && tid < 416) {
                int u = tid >> 3, bp = tid & 7;
                float v0 = 0.f, v1 = 0.f;
                if (u < H) {
                    int hx = hidx(u) + 2 * bp;
                    float2 dir = g2[(GR3 + u) * GPU + bp];
                    float2 diz = g2[(GR3 + 51 + u) * GPU + bp];
                    float2 din = g2[(GR3 + 102 + u) * GPU + bp];
                    float2 d2r = g2[(GR2 + u) * GPU + bp];
                    float2 d2z = g2[(GR2 + 51 + u) * GPU + bp];
                    float2 d2n = g2[(GR2 + 102 + u) * GPU + bp];
                    float2 hold = *(const float2*)(h2c + hx);
                    float r0 = sigf(dir.x + d2r.x), r1 = sigf(dir.y + d2r.y);
                    float z0 = sigf(diz.x + d2z.x), z1 = sigf(diz.y + d2z.y);
                    float n0 = tanh_f(fmaf(r0, d2n.x, din.x));
                    float n1 = tanh_f(fmaf(r1, d2n.y, din.y));
                    float h0 = n0 + z0 * (hold.x - n0);
                    float h1 = n1 + z1 * (hold.y - n1);
                    *(float2*)(h2n + hx) = make_float2(h0, h1);
                    float wl = tabs[6 * H + u];
                    v0 = wl * h0; v1 = wl * h1;
                }
                ull pv = pack2(v0, v1);
                ull t;
                t = __shfl_xor_sync(0xFFFFFFFFu, pv, 8);  ADDF2(pv, t);
                t = __shfl_xor_sync(0xFFFFFFFFu, pv, 16); ADDF2(pv, t);
                if ((lane & 24) == 0) {
                    float2 pr = unpack2(pv);
                    *(float2*)(red + par * REDS + (tid >> 5) * 16 + 2 * (lane & 7)) = pr;
                }
            }
            // ---- L1 pointwise (threads 104..511) ----
            int jj = tid - 104;
            if (jj >= 0 && jj < 408) {
                int u = jj >> 3, bp = jj & 7;
                int hx = hidx(u) + 2 * bp;
                float2 x2 = *(const float2*)(xbuf + 2 * bp);
                float2 ar = g2[u * GPU + bp];
                float2 az = g2[(51 + u) * GPU + bp];
                float2 an = g2[(102 + u) * GPU + bp];
                float2 hold = *(const float2*)(h1c + hx);
                float w1r = tabs[u], w1z = tabs[H + u], w1n = tabs[2 * H + u];
                float c1r = tabs[3 * H + u], c1z = tabs[4 * H + u], c1n = tabs[5 * H + u];
                float r0 = sigf(fmaf(x2.x, w1r, c1r) + ar.x);
                float r1 = sigf(fmaf(x2.y, w1r, c1r) + ar.y);
                float z0 = sigf(fmaf(x2.x, w1z, c1z) + az.x);
                float z1 = sigf(fmaf(x2.y, w1z, c1z) + az.y);
                float n0 = tanh_f(fmaf(x2.x, w1n, c1n) + r0 * an.x);
                float n1 = tanh_f(fmaf(x2.y, w1n, c1n) + r1 * an.y);
                float h0 = n0 + z0 * (hold.x - n0);
                float h1 = n1 + z1 * (hold.y - n1);
                *(float2*)(h1n + hx) = make_float2(h0, h1);
            }
            __syncthreads();
        } else {
            // ---- future mode: L2 (+atomic o) -> sync -> out + L1 -> sync ----
            float* oa = oacc + par * 16;
            if (tid < 408) {
                int u = tid >> 3, bp = tid & 7;
                int hx = hidx(u) + 2 * bp;
                float2 dir = g2[(GR3 + u) * GPU + bp];
                float2 diz = g2[(GR3 + 51 + u) * GPU + bp];
                float2 din = g2[(GR3 + 102 + u) * GPU + bp];
                float2 d2r = g2[(GR2 + u) * GPU + bp];
                float2 d2z = g2[(GR2 + 51 + u) * GPU + bp];
                float2 d2n = g2[(GR2 + 102 + u) * GPU + bp];
                float2 hold = *(const float2*)(h2c + hx);
                float r0 = sigf(dir.x + d2r.x), r1 = sigf(dir.y + d2r.y);
                float z0 = sigf(diz.x + d2z.x), z1 = sigf(diz.y + d2z.y);
                float n0 = tanh_f(fmaf(r0, d2n.x, din.x));
                float n1 = tanh_f(fmaf(r1, d2n.y, din.y));
                float h0 = n0 + z0 * (hold.x - n0);
                float h1 = n1 + z1 * (hold.y - n1);
                *(float2*)(h2n + hx) = make_float2(h0, h1);
                float wl = tabs[6 * H + u];
                atomicAdd(&oa[2 * bp],     wl * h0);
                atomicAdd(&oa[2 * bp + 1], wl * h1);
            }
            __syncthreads();
            if (tid < BB)
                out[(size_t)(gb0 + tid) * TOT + (i - 1)] = oa[tid] + blin;
            int jj = tid - 104;
            if (jj >= 0 && jj < 408) {
                int u = jj >> 3, bp = jj & 7;
                int hx = hidx(u) + 2 * bp;
                float2 x2 = *(const float2*)(oa + 2 * bp);
                x2.x += blin; x2.y += blin;
                float2 ar = g2[u * GPU + bp];
                float2 az = g2[(51 + u) * GPU + bp];
                float2 an = g2[(102 + u) * GPU + bp];
                float2 hold = *(const float2*)(h1c + hx);
                float w1r = tabs[u], w1z = tabs[H + u], w1n = tabs[2 * H + u];
                float c1r = tabs[3 * H + u], c1z = tabs[4 * H + u], c1n = tabs[5 * H + u];
                float r0 = sigf(fmaf(x2.x, w1r, c1r) + ar.x);
                float r1 = sigf(fmaf(x2.y, w1r, c1r) + ar.y);
                float z0 = sigf(fmaf(x2.x, w1z, c1z) + az.x);
                float z1 = sigf(fmaf(x2.y, w1z, c1z) + az.y);
                float n0 = tanh_f(fmaf(x2.x, w1n, c1n) + r0 * an.x);
                float n1 = tanh_f(fmaf(x2.y, w1n, c1n) + r1 * an.y);
                float h0 = n0 + z0 * (hold.x - n0);
                float h1 = n1 + z1 * (hold.y - n1);
                *(float2*)(h1n + hx) = make_float2(h0, h1);
            }
            __syncthreads();
        }
    }
}

extern "C" void kernel_launch(void* const* d_in, const int* in_sizes, int n_in,
                              void* d_out, int out_size) {
    const float* input = (const float*)d_in[0];
    const float* w_ih1 = (const float*)d_in[2];
    const float* w_hh1 = (const float*)d_in[3];
    const float* b_ih1 = (const float*)d_in[4];
    const float* b_hh1 = (const float*)d_in[5];
    const float* w_ih2 = (const float*)d_in[6];
    const float* w_hh2 = (const float*)d_in[7];
    const float* b_ih2 = (const float*)d_in[8];
    const float* b_hh2 = (const float*)d_in[9];
    const float* w_lin = (const float*)d_in[10];
    const float* b_lin = (const float*)d_in[11];

    const int B   = 2048;
    const int T   = in_sizes[0] / B;
    const int TOT = out_size / B;
    const int F   = TOT - T;

    size_t smem = (size_t)(4 * HSTRIDE + GROWS * GPF + 7 * H + 1 + BB + 2 * BB + 2 * REDS) * sizeof(float);
    cudaFuncSetAttribute(gru2_kernel, cudaFuncAttributeMaxDynamicSharedMemorySize, (int)smem);

    gru2_kernel<<<B / BB, NTHREADS, smem>>>(
        input, w_ih1, w_hh1, b_ih1, b_hh1,
        w_ih2, w_hh2, b_ih2, b_hh2,
        w_lin, b_lin, (float*)d_out, T, F);
}